// round 3
// baseline (speedup 1.0000x reference)
#include <cuda_runtime.h>
#include <cstdint>
#include <cstddef>

// Problem constants (fixed by the reference)
#define M_TOK  8192     // B*S = 4*2048
#define D_IN   4096
#define D_OUT  4096
#define NE     32       // experts
#define RK     16       // rank per expert
#define ER     512      // NE*RK
#define SCALING 2.0f    // lora_alpha / r

// Scratch (static device allocations are the sanctioned workaround)
__device__ float g_axw[(size_t)M_TOK * ER];   // 16 MB: (x@A^T)*w*scaling
__device__ float g_w[(size_t)M_TOK * NE];     //  1 MB: dense gate weights * SCALING

// ---------------------------------------------------------------------------
// helpers
// ---------------------------------------------------------------------------
__device__ __forceinline__ float f2tf32(float x) {
    uint32_t r;
    asm("cvt.rna.tf32.f32 %0, %1;" : "=r"(r) : "f"(x));
    return __uint_as_float(r);
}

__device__ __forceinline__ void mma_tf32(float* c, const uint32_t* a, const uint32_t* b) {
    asm volatile(
        "mma.sync.aligned.m16n8k8.row.col.f32.tf32.tf32.f32 "
        "{%0,%1,%2,%3}, {%4,%5,%6,%7}, {%8,%9}, {%0,%1,%2,%3};\n"
        : "+f"(c[0]), "+f"(c[1]), "+f"(c[2]), "+f"(c[3])
        : "r"(a[0]), "r"(a[1]), "r"(a[2]), "r"(a[3]),
          "r"(b[0]), "r"(b[1]));
}

// ---------------------------------------------------------------------------
// Kernel 1: gating, 32 tokens per block (amortizes gate_w traffic 32x).
// logits = x . gate_w^T ; top-2 softmax renormalized ; dense weights*SCALING.
// Thread layout: lane = token (0..31), warp = expert group (4 experts/warp).
// ---------------------------------------------------------------------------
#define GT_TOK 32
#define GT_DC  128   // D-chunk
#define GT_LDX 132   // xs row stride (floats): 132*4B=528B, 16B-aligned, bank-friendly

__global__ __launch_bounds__(256)
void gate_kernel(const float* __restrict__ x,
                 const float* __restrict__ gw,
                 float* __restrict__ wout)
{
    __shared__ float xs[GT_TOK][GT_LDX];   // 16.5 KB
    __shared__ float gs[NE][GT_DC];        // 16 KB
    __shared__ float logits[GT_TOK][NE + 1];
    __shared__ float sval[GT_TOK][2];
    __shared__ int   sidx[GT_TOK][2];

    const int t   = threadIdx.x;
    const int tok = t & 31;        // lane within warp
    const int eg  = t >> 5;        // warp id: experts 4*eg .. 4*eg+3
    const size_t tok0 = (size_t)blockIdx.x * GT_TOK;

    float acc[4] = {0.f, 0.f, 0.f, 0.f};

    for (int d0 = 0; d0 < D_IN; d0 += GT_DC) {
        __syncthreads();   // previous chunk's readers done before overwrite
        // load x chunk: 32 tok x 128 d = 1024 float4, 4 per thread
        #pragma unroll
        for (int i = 0; i < 4; i++) {
            const int idx4 = t + 256 * i;
            const int row  = idx4 >> 5;        // token 0..31
            const int col4 = (idx4 & 31) * 4;  // d offset 0..124
            float4 v = *(const float4*)&x[(tok0 + row) * D_IN + d0 + col4];
            *(float4*)&xs[row][col4] = v;
            float4 g = *(const float4*)&gw[(size_t)row * D_IN + d0 + col4]; // row = expert
            *(float4*)&gs[row][col4] = g;
        }
        __syncthreads();
        // accumulate: each thread: 1 token x 4 experts
        #pragma unroll 8
        for (int dq = 0; dq < GT_DC; dq += 4) {
            float4 xv = *(const float4*)&xs[tok][dq];
            #pragma unroll
            for (int j = 0; j < 4; j++) {
                float4 gv = *(const float4*)&gs[eg * 4 + j][dq];  // warp-uniform broadcast
                acc[j] += xv.x * gv.x + xv.y * gv.y + xv.z * gv.z + xv.w * gv.w;
            }
        }
    }
    __syncthreads();
    #pragma unroll
    for (int j = 0; j < 4; j++) logits[tok][eg * 4 + j] = acc[j];
    __syncthreads();

    // top-2 per token: threads 0..31, one token each (logits padded -> conflict-free)
    if (t < GT_TOK) {
        int   i1 = 0; float v1 = logits[t][0];
        #pragma unroll
        for (int k = 1; k < NE; k++) { float v = logits[t][k]; if (v > v1) { v1 = v; i1 = k; } }
        int   i2 = -1; float v2 = -3.0e38f;
        #pragma unroll
        for (int k = 0; k < NE; k++) { float v = logits[t][k]; if (k != i1 && v > v2) { v2 = v; i2 = k; } }
        // renormalized top-2 softmax: w1 = 1/(1+exp(l2-l1)), w2 = 1-w1
        float p1 = 1.0f / (1.0f + expf(v2 - v1));
        sidx[t][0] = i1; sidx[t][1] = i2;
        sval[t][0] = p1 * SCALING; sval[t][1] = (1.0f - p1) * SCALING;
    }
    __syncthreads();

    // write dense scaled weights: 1024 outputs, 4 per thread, coalesced
    #pragma unroll
    for (int i = 0; i < 4; i++) {
        const int idx = t + 256 * i;
        const int tk  = idx >> 5;
        const int e   = idx & 31;
        float v = 0.f;
        if (e == sidx[tk][0]) v = sval[tk][0];
        else if (e == sidx[tk][1]) v = sval[tk][1];
        wout[(tok0 + tk) * NE + e] = v;
    }
}

// ---------------------------------------------------------------------------
// Kernel 2/3: tiled TF32 tensor-core GEMM with two K-segments.
//   C[m,n] = sum_k A1[m,k]*W1[n,k]  (+ sum_k A2[m,k]*W2[n,k] if K2>0)
// EPI==1: multiply output by wg[m*NE + n/16] (LoRA gate weighting)
// BM=128, BN=128, BK=16, 256 threads, 2x4 warp grid, 64x32 warp tile.
// Double-buffered smem: one __syncthreads per K-tile.
// ---------------------------------------------------------------------------
#define BM  128
#define BN  128
#define BK  16
#define LDT 20   // padded smem row stride (floats); 20*4B = 80B, 16B-aligned
#define TSZ (BM * LDT)

template<int EPI>
__global__ __launch_bounds__(256)
void gemm_dual_kernel(const float* __restrict__ A1, const float* __restrict__ W1, int K1,
                      const float* __restrict__ A2, const float* __restrict__ W2, int K2,
                      float* __restrict__ Cout, int N,
                      const float* __restrict__ wg)
{
    __shared__ float As[2 * TSZ];
    __shared__ float Bs[2 * TSZ];

    const int t  = threadIdx.x;
    const int m0 = blockIdx.y * BM;
    const int n0 = blockIdx.x * BN;

    const int warp = t >> 5;
    const int lane = t & 31;
    const int wm = (warp & 1) * 64;   // warp m-offset in tile
    const int wn = (warp >> 1) * 32;  // warp n-offset in tile
    const int g  = lane >> 2;         // groupID
    const int tg = lane & 3;          // threadID in group

    float acc[4][4][4];
    #pragma unroll
    for (int i = 0; i < 4; i++)
        #pragma unroll
        for (int j = 0; j < 4; j++)
            #pragma unroll
            for (int k = 0; k < 4; k++)
                acc[i][j][k] = 0.f;

    // cooperative loader: tile is 128 rows x 4 float4-cols; 2 float4 per thread
    const int r0 = t >> 2;
    const int c4 = (t & 3) * 4;

    float4 pa0, pa1, pb0, pb1;

    auto load_gmem = [&](const float* A, const float* W, int K, int kb) {
        const float* ap = A + (size_t)(m0 + r0) * K + kb + c4;
        pa0 = *(const float4*)ap;
        pa1 = *(const float4*)(ap + (size_t)64 * K);
        const float* bp = W + (size_t)(n0 + r0) * K + kb + c4;
        pb0 = *(const float4*)bp;
        pb1 = *(const float4*)(bp + (size_t)64 * K);
    };

    auto store_smem = [&](int buf) {
        float* as = As + buf * TSZ;
        float* bs = Bs + buf * TSZ;
        float4 q;
        q.x = f2tf32(pa0.x); q.y = f2tf32(pa0.y); q.z = f2tf32(pa0.z); q.w = f2tf32(pa0.w);
        *(float4*)&as[r0 * LDT + c4] = q;
        q.x = f2tf32(pa1.x); q.y = f2tf32(pa1.y); q.z = f2tf32(pa1.z); q.w = f2tf32(pa1.w);
        *(float4*)&as[(r0 + 64) * LDT + c4] = q;
        q.x = f2tf32(pb0.x); q.y = f2tf32(pb0.y); q.z = f2tf32(pb0.z); q.w = f2tf32(pb0.w);
        *(float4*)&bs[r0 * LDT + c4] = q;
        q.x = f2tf32(pb1.x); q.y = f2tf32(pb1.y); q.z = f2tf32(pb1.z); q.w = f2tf32(pb1.w);
        *(float4*)&bs[(r0 + 64) * LDT + c4] = q;
    };

    auto compute = [&](int buf) {
        const float* as = As + buf * TSZ;
        const float* bs = Bs + buf * TSZ;
        #pragma unroll
        for (int ks = 0; ks < BK; ks += 8) {
            uint32_t af[4][4], bf[4][2];
            #pragma unroll
            for (int i = 0; i < 4; i++) {
                const int mb = wm + i * 16;
                af[i][0] = __float_as_uint(as[(mb + g    ) * LDT + ks + tg    ]);
                af[i][1] = __float_as_uint(as[(mb + g + 8) * LDT + ks + tg    ]);
                af[i][2] = __float_as_uint(as[(mb + g    ) * LDT + ks + tg + 4]);
                af[i][3] = __float_as_uint(as[(mb + g + 8) * LDT + ks + tg + 4]);
            }
            #pragma unroll
            for (int j = 0; j < 4; j++) {
                const int nb = wn + j * 8 + g;
                bf[j][0] = __float_as_uint(bs[nb * LDT + ks + tg    ]);
                bf[j][1] = __float_as_uint(bs[nb * LDT + ks + tg + 4]);
            }
            #pragma unroll
            for (int i = 0; i < 4; i++)
                #pragma unroll
                for (int j = 0; j < 4; j++)
                    mma_tf32(acc[i][j], af[i], bf[j]);
        }
    };

    // run one K-segment with double-buffered smem (one barrier per tile)
    auto run_segment = [&](const float* A, const float* W, int K) {
        const int nk = K / BK;
        load_gmem(A, W, K, 0);
        store_smem(0);
        __syncthreads();
        for (int kb = 0; kb < nk; kb++) {
            const int  cur      = kb & 1;
            const bool has_next = (kb + 1 < nk);
            if (has_next) load_gmem(A, W, K, (kb + 1) * BK);  // gmem -> regs
            compute(cur);                                     // smem buf[cur]
            if (has_next) store_smem(cur ^ 1);                // regs -> buf[!cur]
            __syncthreads();
        }
    };

    run_segment(A1, W1, K1);
    if (K2 > 0) run_segment(A2, W2, K2);

    // epilogue
    #pragma unroll
    for (int i = 0; i < 4; i++) {
        const int mrow = m0 + wm + i * 16 + g;
        #pragma unroll
        for (int j = 0; j < 4; j++) {
            const int ncol = n0 + wn + j * 8 + tg * 2;
            float s0 = 1.f, s1 = 1.f;
            if (EPI) {
                s0 = wg[(size_t)mrow       * NE + (ncol >> 4)];
                s1 = wg[(size_t)(mrow + 8) * NE + (ncol >> 4)];
            }
            float2 v0; v0.x = acc[i][j][0] * s0; v0.y = acc[i][j][1] * s0;
            float2 v1; v1.x = acc[i][j][2] * s1; v1.y = acc[i][j][3] * s1;
            *(float2*)&Cout[(size_t)mrow       * N + ncol] = v0;
            *(float2*)&Cout[(size_t)(mrow + 8) * N + ncol] = v1;
        }
    }
}

// ---------------------------------------------------------------------------
// launch
// ---------------------------------------------------------------------------
extern "C" void kernel_launch(void* const* d_in, const int* in_sizes, int n_in,
                              void* d_out, int out_size) {
    const float* x      = (const float*)d_in[0];  // [4,2048,4096]
    const float* base_w = (const float*)d_in[1];  // [4096,4096]
    const float* gate_w = (const float*)d_in[2];  // [32,4096]
    const float* lora_A = (const float*)d_in[3];  // [512,4096]
    const float* lora_B = (const float*)d_in[4];  // [4096,512]
    float* out = (float*)d_out;                   // [4,2048,4096]

    float *axw = nullptr, *wbuf = nullptr;
    cudaGetSymbolAddress((void**)&axw,  g_axw);
    cudaGetSymbolAddress((void**)&wbuf, g_w);

    // 1) gate weights (dense, scaled)
    gate_kernel<<<M_TOK / GT_TOK, 256>>>(x, gate_w, wbuf);

    // 2) axw = (x @ lora_A^T) * w_expand * SCALING   [8192, 512]
    {
        dim3 grid(ER / BN, M_TOK / BM);   // (4, 64)
        gemm_dual_kernel<1><<<grid, 256>>>(x, lora_A, D_IN,
                                           nullptr, nullptr, 0,
                                           axw, ER, wbuf);
    }

    // 3) out = x @ base_w^T + axw @ lora_B^T         [8192, 4096]
    {
        dim3 grid(D_OUT / BN, M_TOK / BM); // (32, 64)
        gemm_dual_kernel<0><<<grid, 256>>>(x, base_w, D_IN,
                                           axw, lora_B, ER,
                                           out, D_OUT, nullptr);
    }
}

// round 11
// speedup vs baseline: 1.4159x; 1.4159x over previous
#include <cuda_runtime.h>
#include <cstdint>
#include <cstddef>

// Problem constants
#define M_TOK  8192
#define D_IN   4096
#define D_OUT  4096
#define NE     32
#define ER     512
#define SCALING 2.0f

// Scratch (__device__ globals are the sanctioned workaround)
__device__ float g_xr [(size_t)M_TOK * D_IN];   // 128 MB: tf32-rounded x
__device__ float g_bwr[(size_t)D_OUT * D_IN];   //  64 MB: tf32-rounded base_w
__device__ float g_lar[(size_t)ER * D_IN];      //   8 MB: tf32-rounded lora_A
__device__ float g_lbr[(size_t)D_OUT * ER];     //   8 MB: tf32-rounded lora_B
__device__ float g_axw[(size_t)M_TOK * ER];     //  16 MB: (x@A^T)*w*SCALING (tf32-rounded)
__device__ float g_w  [(size_t)M_TOK * NE];     //   1 MB: gate weights * SCALING

// ---------------------------------------------------------------------------
// helpers
// ---------------------------------------------------------------------------
__device__ __forceinline__ uint32_t smem_u32(const void* p) {
    uint32_t a;
    asm("{ .reg .u64 t; cvta.to.shared.u64 t, %1; cvt.u32.u64 %0, t; }" : "=r"(a) : "l"(p));
    return a;
}
__device__ __forceinline__ float f2tf32(float x) {
    uint32_t r; asm("cvt.rna.tf32.f32 %0, %1;" : "=r"(r) : "f"(x));
    return __uint_as_float(r);
}
__device__ __forceinline__ void mma_tf32(float* c, const uint32_t* a, const uint32_t* b) {
    asm volatile(
        "mma.sync.aligned.m16n8k8.row.col.f32.tf32.tf32.f32 "
        "{%0,%1,%2,%3}, {%4,%5,%6,%7}, {%8,%9}, {%0,%1,%2,%3};\n"
        : "+f"(c[0]), "+f"(c[1]), "+f"(c[2]), "+f"(c[3])
        : "r"(a[0]), "r"(a[1]), "r"(a[2]), "r"(a[3]),
          "r"(b[0]), "r"(b[1]));
}
#define CP_ASYNC16(dst, src) \
    asm volatile("cp.async.cg.shared.global [%0], [%1], 16;" :: "r"(dst), "l"(src) : "memory")
#define CP_COMMIT() asm volatile("cp.async.commit_group;" ::: "memory")
#define CP_WAIT(n)  asm volatile("cp.async.wait_group %0;" :: "n"(n) : "memory")

// ---------------------------------------------------------------------------
// Kernel 0: elementwise tf32 rounding (RNA), vectorized
// ---------------------------------------------------------------------------
__global__ __launch_bounds__(256)
void round_kernel(const float* __restrict__ in, float* __restrict__ out, int n4) {
    const float4* i4 = (const float4*)in;
    float4* o4 = (float4*)out;
    for (int i = blockIdx.x * blockDim.x + threadIdx.x; i < n4; i += gridDim.x * blockDim.x) {
        float4 q = i4[i];
        q.x = f2tf32(q.x); q.y = f2tf32(q.y);
        q.z = f2tf32(q.z); q.w = f2tf32(q.w);
        o4[i] = q;
    }
}

// ---------------------------------------------------------------------------
// Kernel 1: gating, 32 tokens/block (measured R3: 162us). Reads original x.
// ---------------------------------------------------------------------------
#define GT_TOK 32
#define GT_DC  128
#define GT_LDX 132

__global__ __launch_bounds__(256)
void gate_kernel(const float* __restrict__ x,
                 const float* __restrict__ gw,
                 float* __restrict__ wout)
{
    __shared__ float xs[GT_TOK][GT_LDX];
    __shared__ float gs[NE][GT_DC];
    __shared__ float logits[GT_TOK][NE + 1];
    __shared__ float sval[GT_TOK][2];
    __shared__ int   sidx[GT_TOK][2];

    const int t   = threadIdx.x;
    const int tok = t & 31;
    const int eg  = t >> 5;
    const size_t tok0 = (size_t)blockIdx.x * GT_TOK;

    float acc[4] = {0.f, 0.f, 0.f, 0.f};

    for (int d0 = 0; d0 < D_IN; d0 += GT_DC) {
        __syncthreads();
        #pragma unroll
        for (int i = 0; i < 4; i++) {
            const int idx4 = t + 256 * i;
            const int row  = idx4 >> 5;
            const int col4 = (idx4 & 31) * 4;
            float4 v = *(const float4*)&x[(tok0 + row) * D_IN + d0 + col4];
            *(float4*)&xs[row][col4] = v;
            float4 g = *(const float4*)&gw[(size_t)row * D_IN + d0 + col4];
            *(float4*)&gs[row][col4] = g;
        }
        __syncthreads();
        #pragma unroll 8
        for (int dq = 0; dq < GT_DC; dq += 4) {
            float4 xv = *(const float4*)&xs[tok][dq];
            #pragma unroll
            for (int j = 0; j < 4; j++) {
                float4 gv = *(const float4*)&gs[eg * 4 + j][dq];
                acc[j] += xv.x * gv.x + xv.y * gv.y + xv.z * gv.z + xv.w * gv.w;
            }
        }
    }
    __syncthreads();
    #pragma unroll
    for (int j = 0; j < 4; j++) logits[tok][eg * 4 + j] = acc[j];
    __syncthreads();

    if (t < GT_TOK) {
        int   i1 = 0; float v1 = logits[t][0];
        #pragma unroll
        for (int k = 1; k < NE; k++) { float v = logits[t][k]; if (v > v1) { v1 = v; i1 = k; } }
        int   i2 = -1; float v2 = -3.0e38f;
        #pragma unroll
        for (int k = 0; k < NE; k++) { float v = logits[t][k]; if (k != i1 && v > v2) { v2 = v; i2 = k; } }
        float p1 = 1.0f / (1.0f + expf(v2 - v1));
        sidx[t][0] = i1; sidx[t][1] = i2;
        sval[t][0] = p1 * SCALING; sval[t][1] = (1.0f - p1) * SCALING;
    }
    __syncthreads();

    #pragma unroll
    for (int i = 0; i < 4; i++) {
        const int idx = t + 256 * i;
        const int tk  = idx >> 5;
        const int e   = idx & 31;
        float v = 0.f;
        if (e == sidx[tk][0]) v = sval[tk][0];
        else if (e == sidx[tk][1]) v = sval[tk][1];
        wout[(tok0 + tk) * NE + e] = v;
    }
}

// ---------------------------------------------------------------------------
// Kernel 2/3: multistage cp.async TF32 mma.sync GEMM, dual K-segment.
//   C[m,n] = sum A1[m,:]W1[n,:] (+ sum A2[m,:]W2[n,:])
// Inputs are PRE-ROUNDED to tf32 (no converts in mainloop).
// BM=BN=128, BK=32, 3 stages, 256 threads, 2x4 warp grid, 64x32 warp tile.
// Smem row stride 36 floats: cp.async 16B-aligned AND conflict-free fragment
// LDS (bank = (4g+tg) mod 32, all distinct per warp).
// One __syncthreads per K-tile: any thread past barrier(kt) implies all
// threads finished compute(kt-1), so cp.async reissue into buf (kt-1)%3 is safe.
// EPI==1: scale output by wg[row*NE + col/16] and re-round to tf32 (feeds gemm3).
// ---------------------------------------------------------------------------
#define BK     32
#define LDA    36                  // padded row stride (floats)
#define STRIDE (128 * LDA)         // floats per tile buffer
#define STAGES 3

template<int EPI>
__global__ __launch_bounds__(256, 2)
void mma_gemm(const float* __restrict__ A1, const float* __restrict__ W1, int k1, int nt1,
              const float* __restrict__ A2, const float* __restrict__ W2, int k2, int nt2,
              float* __restrict__ C, int Nout,
              const float* __restrict__ wg)
{
    extern __shared__ float sm[];   // [3 A-stages][3 B-stages]

    const int t    = threadIdx.x;
    const int warp = t >> 5;
    const int lane = t & 31;
    const int m0   = blockIdx.y * 128;
    const int n0   = blockIdx.x * 128;
    const int wm   = (warp & 1) * 64;
    const int wn   = (warp >> 1) * 32;
    const int g    = lane >> 2;
    const int tg   = lane & 3;
    const int nt   = nt1 + nt2;

    float acc[4][4][4];
    #pragma unroll
    for (int i = 0; i < 4; i++)
        #pragma unroll
        for (int j = 0; j < 4; j++)
            #pragma unroll
            for (int k = 0; k < 4; k++)
                acc[i][j][k] = 0.f;

    const uint32_t smU = smem_u32(sm);

    auto issue = [&](int kt, int s) {
        const float* As; const float* Ws; int ks, koff;
        if (kt < nt1) { As = A1; Ws = W1; ks = k1; koff = kt * BK; }
        else          { As = A2; Ws = W2; ks = k2; koff = (kt - nt1) * BK; }
        const uint32_t aU = smU + (uint32_t)(s * STRIDE) * 4u;
        const uint32_t bU = smU + (uint32_t)((STAGES + s) * STRIDE) * 4u;
        #pragma unroll
        for (int i = 0; i < 4; i++) {
            const int ch = i * 256 + t;
            const int row = ch >> 3;            // 0..127
            const int kc  = (ch & 7) * 4;       // 0..28
            CP_ASYNC16(aU + (uint32_t)(row * LDA + kc) * 4u,
                       As + (size_t)(m0 + row) * ks + koff + kc);
            CP_ASYNC16(bU + (uint32_t)(row * LDA + kc) * 4u,
                       Ws + (size_t)(n0 + row) * ks + koff + kc);
        }
    };

    // prologue: stages 0,1 in flight
    issue(0, 0); CP_COMMIT();
    issue(1, 1); CP_COMMIT();

    for (int kt = 0; kt < nt; kt++) {
        const int s = kt % STAGES;
        CP_WAIT(1);                 // tile kt's group complete
        __syncthreads();

        const float* as = sm + s * STRIDE;
        const float* bs = sm + (STAGES + s) * STRIDE;

        #pragma unroll
        for (int ks = 0; ks < BK; ks += 8) {
            uint32_t af[4][4], bf[4][2];
            #pragma unroll
            for (int i = 0; i < 4; i++) {
                const int mb = wm + i * 16;
                af[i][0] = __float_as_uint(as[(mb + g    ) * LDA + ks + tg    ]);
                af[i][1] = __float_as_uint(as[(mb + g + 8) * LDA + ks + tg    ]);
                af[i][2] = __float_as_uint(as[(mb + g    ) * LDA + ks + tg + 4]);
                af[i][3] = __float_as_uint(as[(mb + g + 8) * LDA + ks + tg + 4]);
            }
            #pragma unroll
            for (int j = 0; j < 4; j++) {
                const int nb = wn + j * 8 + g;
                bf[j][0] = __float_as_uint(bs[nb * LDA + ks + tg    ]);
                bf[j][1] = __float_as_uint(bs[nb * LDA + ks + tg + 4]);
            }
            #pragma unroll
            for (int i = 0; i < 4; i++)
                #pragma unroll
                for (int j = 0; j < 4; j++)
                    mma_tf32(acc[i][j], af[i], bf[j]);
        }

        if (kt + 2 < nt) issue(kt + 2, (kt + 2) % STAGES);
        CP_COMMIT();                // commit (possibly empty) keeps group count aligned
    }

    // epilogue
    #pragma unroll
    for (int i = 0; i < 4; i++) {
        const int mrow = m0 + wm + i * 16 + g;
        #pragma unroll
        for (int j = 0; j < 4; j++) {
            const int ncol = n0 + wn + j * 8 + tg * 2;
            float s0 = 1.f, s1 = 1.f;
            if (EPI) {
                s0 = wg[(size_t)mrow       * NE + (ncol >> 4)];
                s1 = wg[(size_t)(mrow + 8) * NE + (ncol >> 4)];
            }
            float2 v0, v1;
            if (EPI) {   // feeds gemm3 as a tf32 operand: round now
                v0.x = f2tf32(acc[i][j][0] * s0); v0.y = f2tf32(acc[i][j][1] * s0);
                v1.x = f2tf32(acc[i][j][2] * s1); v1.y = f2tf32(acc[i][j][3] * s1);
            } else {
                v0.x = acc[i][j][0]; v0.y = acc[i][j][1];
                v1.x = acc[i][j][2]; v1.y = acc[i][j][3];
            }
            *(float2*)&C[(size_t)mrow       * Nout + ncol] = v0;
            *(float2*)&C[(size_t)(mrow + 8) * Nout + ncol] = v1;
        }
    }
}

// ---------------------------------------------------------------------------
// launch
// ---------------------------------------------------------------------------
extern "C" void kernel_launch(void* const* d_in, const int* in_sizes, int n_in,
                              void* d_out, int out_size) {
    const float* x      = (const float*)d_in[0];
    const float* base_w = (const float*)d_in[1];
    const float* gate_w = (const float*)d_in[2];
    const float* lora_A = (const float*)d_in[3];
    const float* lora_B = (const float*)d_in[4];
    float* out = (float*)d_out;

    float *xr, *bwr, *lar, *lbr, *axw, *wbuf;
    cudaGetSymbolAddress((void**)&xr,   g_xr);
    cudaGetSymbolAddress((void**)&bwr,  g_bwr);
    cudaGetSymbolAddress((void**)&lar,  g_lar);
    cudaGetSymbolAddress((void**)&lbr,  g_lbr);
    cudaGetSymbolAddress((void**)&axw,  g_axw);
    cudaGetSymbolAddress((void**)&wbuf, g_w);

    const int smem = STAGES * 2 * STRIDE * 4;   // 110592 B
    cudaFuncSetAttribute(mma_gemm<0>, cudaFuncAttributeMaxDynamicSharedMemorySize, smem);
    cudaFuncSetAttribute(mma_gemm<1>, cudaFuncAttributeMaxDynamicSharedMemorySize, smem);

    // 0) pre-round GEMM operands to tf32 (RNA)
    round_kernel<<<2048, 256>>>(x,      xr,  (int)((size_t)M_TOK * D_IN / 4));
    round_kernel<<<1024, 256>>>(base_w, bwr, (int)((size_t)D_OUT * D_IN / 4));
    round_kernel<<<128,  256>>>(lora_A, lar, (int)((size_t)ER * D_IN / 4));
    round_kernel<<<128,  256>>>(lora_B, lbr, (int)((size_t)D_OUT * ER / 4));

    // 1) gate weights (original x)
    gate_kernel<<<M_TOK / GT_TOK, 256>>>(x, gate_w, wbuf);

    // 2) axw = (x @ lora_A^T) * w * SCALING   [8192, 512] (tf32-rounded)
    {
        dim3 grid(ER / 128, M_TOK / 128);     // (4, 64)
        mma_gemm<1><<<grid, 256, smem>>>(xr, lar, D_IN, D_IN / BK,
                                         nullptr, nullptr, 0, 0,
                                         axw, ER, wbuf);
    }

    // 3) out = x @ base_w^T + axw @ lora_B^T  [8192, 4096]
    {
        dim3 grid(D_OUT / 128, M_TOK / 128);  // (32, 64)
        mma_gemm<0><<<grid, 256, smem>>>(xr, bwr, D_IN, D_IN / BK,
                                         axw, lbr, ER, ER / BK,
                                         out, D_OUT, nullptr);
    }
}